// round 11
// baseline (speedup 1.0000x reference)
#include <cuda_runtime.h>
#include <math.h>
#include <float.h>
#include <stdint.h>

// Problem constants (fixed by the reference)
#define B_IMG  32
#define D_DIM  256
#define HW_SZ  4096     // H*W = 64*64
#define K_CB   512
#define NCLS   10
#define NSHR   10

// Tiling: 384-thread CTA; thread = (pixel pair 2*(tid&127), group tid>>7)
#define TP     256      // pixels per block
#define NTHR   384
#define NGRP   3        // code groups
#define CPG    19       // usable codes per group (3*19 = 57 >= 51)
#define GSTR   20       // group stride in cbT columns (16B-aligned bases)
#define KTP    64       // cbT row stride
#define CHROWS 32       // d-rows staged per chunk
#define NCHNK  (D_DIM / CHROWS)   // 8

#define F32_INF __int_as_float(0x7f800000)

struct ClassRanges { int lo[NCLS]; int cnt[NCLS]; };

typedef unsigned long long ull;

// ---- packed f32x2 helpers (Blackwell): exact per-lane IEEE fp32 semantics --
__device__ __forceinline__ ull pack2(float x) {
    unsigned int b = __float_as_uint(x);
    ull r;
    asm("mov.b64 %0, {%1, %1};" : "=l"(r) : "r"(b));
    return r;
}
__device__ __forceinline__ void fma2(ull& d, ull a, ull b) {
    asm("fma.rn.f32x2 %0, %1, %2, %0;" : "+l"(d) : "l"(a), "l"(b));
}
__device__ __forceinline__ ull mul2(ull a, ull b) {
    ull r;
    asm("mul.rn.f32x2 %0, %1, %2;" : "=l"(r) : "l"(a), "l"(b));
    return r;
}
__device__ __forceinline__ void add2(ull& d, ull a) {
    asm("add.rn.f32x2 %0, %0, %1;" : "+l"(d) : "l"(a));
}
__device__ __forceinline__ float2 unpack2(ull v) {
    unsigned int lo, hi;
    asm("mov.b64 {%0, %1}, %2;" : "=r"(lo), "=r"(hi) : "l"(v));
    return make_float2(__uint_as_float(lo), __uint_as_float(hi));
}

// ----------------------------------------------------------------------------
// One block: image b, 256 contiguous pixels, 384 threads (12 warps).
// Thread (pp, g) owns pixels {2pp, 2pp+1} and 19 codes (10 packed pairs,
// last pair = (code18, pad)). Codebook slice [lo, lo+cnt) TRANSPOSED in
// smem: cbT[d][col], col = 20*(kk/19) + kk%19 (pads zero, cb_sqr = +inf).
// x staged through smem in 32-row chunks shared by all 3 groups.
//
// Bit-exact replication of the reference fp32 arithmetic (validated R2..R10):
//   A   = in_sqr  : sequential ascending sum of fl(x_d*x_d)  (mul then add)
//   g_k = x . c_k : sequential ascending fused-FMA chain (one register lane)
//   d_k = fl( fl(A + p_k) - 2*g_k );  argmin, first-min tie-break
//   (storage col strictly monotone in code index -> scan order == k order)
// ----------------------------------------------------------------------------
__global__ void __launch_bounds__(NTHR, 2)
vq_kernel(const float* __restrict__ z, const float* __restrict__ cb,
          const int* __restrict__ labels, float* __restrict__ out,
          ClassRanges cr)
{
    extern __shared__ float smem[];
    float* cbT_s = smem;                      // [256 d][KTP]  (64 KB)
    float* p_s   = cbT_s + D_DIM * KTP;       // [KTP] cb_sqr by col (+inf pads)
    float* A_s   = p_s + KTP;                 // [256] in_sqr per pixel
    float* x_s   = A_s + 256;                 // [CHROWS][256] staged x (32 KB)
    float* rs    = x_s + CHROWS * 256;        // [NGRP][256] best distance
    int*   ri    = (int*)(rs + NGRP * 256);   // [NGRP][256] storage cols
    int*   best  = (int*)(ri + NGRP * 256);   // [256]

    const int tid = threadIdx.x;
    const int tx  = tid & 31;
    const int wid = tid >> 5;                 // warp 0..11
    const int pp  = tid & 127;                // pixel pair id
    const int px0 = pp << 1;                  // first owned pixel
    const int grp = tid >> 7;                 // code group 0..2
    const int b   = blockIdx.y;
    const int hw0 = blockIdx.x * TP;

    const int label = labels[b];
    const int lo    = cr.lo[label];
    const int cnt   = cr.cnt[label];          // 50 or 51

    // ---- init p_s to +inf, zero cbT (covers pad columns) ----
    if (tid < KTP) p_s[tid] = F32_INF;
    for (int i = tid; i < D_DIM * (KTP / 4); i += NTHR)
        *(float4*)&cbT_s[i << 2] = make_float4(0.f, 0.f, 0.f, 0.f);
    __syncthreads();

    // ---- build transposed codebook: cbT[d][col] = cb[lo+kk][d] ----
    for (int i = tid; i < 56 * (D_DIM / 4); i += NTHR) {
        const int kk  = i % 56;               // compact code index (cnt<=51)
        const int d4  = (i / 56) << 2;
        if (kk < cnt) {
            const int col = (kk / CPG) * GSTR + (kk % CPG);
            const float4 v = *(const float4*)(cb + (size_t)(lo + kk) * D_DIM + d4);
            cbT_s[(d4 + 0) * KTP + col] = v.x;
            cbT_s[(d4 + 1) * KTP + col] = v.y;
            cbT_s[(d4 + 2) * KTP + col] = v.z;
            cbT_s[(d4 + 3) * KTP + col] = v.w;
        }
    }

    // ---- cb_sqr per code from GLOBAL cb (coalesced); warps 0..7 cover 56 ----
    if (wid < 8) {
        #pragma unroll
        for (int j = 0; j < 7; ++j) {
            const int kk = wid * 7 + j;       // 0..55
            if (kk < cnt) {
                const float* crow = cb + (size_t)(lo + kk) * D_DIM;
                float s = 0.0f;
                #pragma unroll
                for (int d = tx; d < D_DIM; d += 32) {
                    const float v = __ldg(crow + d);
                    s = __fadd_rn(s, __fmul_rn(v, v));
                }
                #pragma unroll
                for (int o = 16; o > 0; o >>= 1)
                    s = __fadd_rn(s, __shfl_xor_sync(0xffffffffu, s, o));
                if (tx == 0) {
                    const int col = (kk / CPG) * GSTR + (kk % CPG);
                    p_s[col] = s;
                }
            }
        }
    }
    __syncthreads();

    // ---- main pass: 8 chunks of 32 d-rows staged through smem ----
    ull acc[10][2];                           // 10 code-pairs x 2 pixels
    #pragma unroll
    for (int j = 0; j < 10; ++j) { acc[j][0] = 0ULL; acc[j][1] = 0ULL; }
    ull asq = 0ULL;                           // in_sqr pair (group 0 only)

    const float* xbase = z + (size_t)b * D_DIM * HW_SZ + hw0;
    const int colbase = grp * GSTR;           // 0 / 20 / 40 (16B-aligned)
    const bool grp0 = (grp == 0);             // warp-uniform

    for (int ch = 0; ch < NCHNK; ++ch) {
        const int dc0 = ch * CHROWS;
        const float* xs = xbase + (size_t)dc0 * HW_SZ;
        __syncthreads();                      // protect x_s reuse
        // stage x chunk [32 d][256 px] (float4, coalesced)
        for (int i = tid; i < CHROWS * 64; i += NTHR) {
            const int row = i >> 6;
            const int c4  = (i & 63) << 2;
            *(float4*)&x_s[(row << 8) + c4] =
                *(const float4*)(xs + (size_t)row * HW_SZ + c4);
        }
        __syncthreads();

        #pragma unroll 2
        for (int dd = 0; dd < CHROWS; ++dd) {
            const ull xp = *(const ull*)&x_s[(dd << 8) + px0];  // LDS.64 pair

            const float* crow = cbT_s + (dc0 + dd) * KTP + colbase;
            const float4 c0 = *(const float4*)(crow + 0);
            const float4 c1 = *(const float4*)(crow + 4);
            const float4 c2 = *(const float4*)(crow + 8);
            const float4 c3 = *(const float4*)(crow + 12);
            const float4 c4 = *(const float4*)(crow + 16);   // [16..19], 19=pad

            if (grp0)                          // bit-exact per-pixel chains
                add2(asq, mul2(xp, xp));

            const float2 xv = unpack2(xp);
            const ull xd0 = pack2(xv.x);
            const ull xd1 = pack2(xv.y);

            const ull k0 = *(const ull*)&c0.x, k1 = *(const ull*)&c0.z;
            const ull k2 = *(const ull*)&c1.x, k3 = *(const ull*)&c1.z;
            const ull k4 = *(const ull*)&c2.x, k5 = *(const ull*)&c2.z;
            const ull k6 = *(const ull*)&c3.x, k7 = *(const ull*)&c3.z;
            const ull k8 = *(const ull*)&c4.x, k9 = *(const ull*)&c4.z;

            fma2(acc[0][0], xd0, k0);  fma2(acc[0][1], xd1, k0);
            fma2(acc[1][0], xd0, k1);  fma2(acc[1][1], xd1, k1);
            fma2(acc[2][0], xd0, k2);  fma2(acc[2][1], xd1, k2);
            fma2(acc[3][0], xd0, k3);  fma2(acc[3][1], xd1, k3);
            fma2(acc[4][0], xd0, k4);  fma2(acc[4][1], xd1, k4);
            fma2(acc[5][0], xd0, k5);  fma2(acc[5][1], xd1, k5);
            fma2(acc[6][0], xd0, k6);  fma2(acc[6][1], xd1, k6);
            fma2(acc[7][0], xd0, k7);  fma2(acc[7][1], xd1, k7);
            fma2(acc[8][0], xd0, k8);  fma2(acc[8][1], xd1, k8);
            fma2(acc[9][0], xd0, k9);  fma2(acc[9][1], xd1, k9);
        }
    }

    if (grp0) *(float2*)&A_s[px0] = unpack2(asq);
    __syncthreads();

    // ---- distances d = fl(fl(A + p) - 2g); per-thread first-min argmin ----
    #pragma unroll
    for (int p = 0; p < 2; ++p) {
        const float Av = A_s[px0 + p];
        float bd = F32_INF;
        int   bi = colbase;
        #pragma unroll
        for (int j = 0; j < 10; ++j) {
            const int c0i = colbase + (j << 1);
            const float2 g = unpack2(acc[j][p]);
            const float d0 = __fadd_rn(__fadd_rn(Av, p_s[c0i]), -(2.0f * g.x));
            const float d1 = __fadd_rn(__fadd_rn(Av, p_s[c0i + 1]), -(2.0f * g.y));
            if (d0 < bd) { bd = d0; bi = c0i; }      // strict <: lowest col wins
            if (d1 < bd) { bd = d1; bi = c0i + 1; }
        }
        rs[grp * 256 + px0 + p] = bd;
        ri[grp * 256 + px0 + p] = bi;
    }
    __syncthreads();

    if (tid < 256) {
        float bd = rs[tid];
        int   bi = ri[tid];
        #pragma unroll
        for (int t2 = 1; t2 < NGRP; ++t2) {
            const float s = rs[t2 * 256 + tid];
            if (s < bd) { bd = s; bi = ri[t2 * 256 + tid]; } // col ascends w/ grp
        }
        best[tid] = bi;
    }
    __syncthreads();

    // ---- epilogue: z_q_x = fl(x + fl(codes - x)), z_q_x_bar = codes ----
    const size_t obase = (size_t)b * D_DIM * HW_SZ + hw0;
    const float* zsrc  = z + obase;
    float* o0 = out + obase;
    float* o1 = out + (size_t)B_IMG * D_DIM * HW_SZ + obase;

    const int ep0 = (tid & 127) << 1;         // 2 pixels
    const int ed0 = tid >> 7;                 // d phase (0..2)
    const int b0 = best[ep0 + 0];
    const int b1 = best[ep0 + 1];

    #pragma unroll 4
    for (int d = ed0; d < D_DIM; d += NGRP) {
        const size_t off = (size_t)d * HW_SZ + ep0;
        const float* crow = cbT_s + (size_t)d * KTP;
        const float2 xv = *(const float2*)(zsrc + off);
        float2 cv;
        cv.x = crow[b0]; cv.y = crow[b1];
        float2 q;
        q.x = __fadd_rn(xv.x, __fadd_rn(cv.x, -xv.x));
        q.y = __fadd_rn(xv.y, __fadd_rn(cv.y, -xv.y));
        *(float2*)(o0 + off) = q;
        *(float2*)(o1 + off) = cv;
    }
}

extern "C" void kernel_launch(void* const* d_in, const int* in_sizes, int n_in,
                              void* d_out, int out_size)
{
    const float* z      = (const float*)d_in[0];
    const float* cb     = (const float*)d_in[1];
    const int*   labels = (const int*)d_in[2];
    float*       out    = (float*)d_out;
    (void)in_sizes; (void)n_in; (void)out_size;

    // Class -> contiguous codebook range, replicating
    // round(linspace(-0.5, NCLS-0.51, K-NSHR)) exactly (double + half-even).
    ClassRanges cr;
    for (int c = 0; c < NCLS; ++c) { cr.lo[c] = 0; cr.cnt[c] = 0; }
    const double step = (((double)NCLS - 0.51) + 0.5) / (double)(K_CB - NSHR - 1);
    int prev = -1;
    for (int i = 0; i < K_CB - NSHR; ++i) {
        const double v = -0.5 + (double)i * step;
        int c = (int)nearbyint(v);
        if (c < 0) c = 0;
        if (c > NCLS - 1) c = NCLS - 1;
        if (c != prev) { cr.lo[c] = i; prev = c; }
        cr.cnt[c] += 1;
    }

    const size_t smem_bytes =
        (size_t)(D_DIM * KTP + KTP + 256 + CHROWS * 256       // cbT, p, A, x
                 + NGRP * 256 + NGRP * 256 + 256) * sizeof(float); // rs, ri, best
    cudaFuncSetAttribute(vq_kernel,
                         cudaFuncAttributeMaxDynamicSharedMemorySize,
                         (int)smem_bytes);

    dim3 grid(HW_SZ / TP, B_IMG);
    vq_kernel<<<grid, NTHR, smem_bytes>>>(z, cb, labels, out, cr);
}